// round 1
// baseline (speedup 1.0000x reference)
#include <cuda_runtime.h>
#include <cuda_bf16.h>
#include <math.h>

// ---------------- problem constants ----------------
#define N_IMG   16384           // B * 2 * NB_DIGITS
#define NBATCH  4096
#define SUMS    199

// ---------------- device scratch (no runtime allocs allowed) ----------------
__device__ float g_pool1[(size_t)N_IMG * 6 * 12 * 12];   // after conv1+pool+relu
__device__ float g_pool2[(size_t)N_IMG * 256];           // after conv2+pool+relu (flattened)
__device__ float g_logp [(size_t)N_IMG * 10];            // per-image log-softmax
__device__ float g_w1t[256 * 120];                       // fc1_w transposed [k][j]
__device__ float g_w2t[120 * 84];
__device__ float g_w3t[84 * 10];

// ---------------- weight transposes (coalesced FC weight reads) ----------------
__global__ void transpose_kernel(const float* __restrict__ w1,
                                 const float* __restrict__ w2,
                                 const float* __restrict__ w3) {
    int i = blockIdx.x * blockDim.x + threadIdx.x;
    if (i < 120 * 256) { int j = i / 256, k = i % 256; g_w1t[k * 120 + j] = w1[i]; }
    if (i < 84 * 120)  { int j = i / 120, k = i % 120; g_w2t[k * 84 + j]  = w2[i]; }
    if (i < 10 * 84)   { int j = i / 84,  k = i % 84;  g_w3t[k * 10 + j]  = w3[i]; }
}

// ---------------- conv1 (1->6, 5x5) + maxpool2 + relu ----------------
// one block per image; image + weights staged in smem
__global__ __launch_bounds__(256) void conv1_kernel(const float* __restrict__ img,
                                                    const float* __restrict__ w,
                                                    const float* __restrict__ b) {
    __shared__ float si[784];
    __shared__ float sw[150];
    __shared__ float sb[6];
    int n = blockIdx.x;
    const float* ip = img + (size_t)n * 784;
    for (int i = threadIdx.x; i < 784; i += 256) si[i] = ip[i];
    if (threadIdx.x < 150) sw[threadIdx.x] = w[threadIdx.x];
    if (threadIdx.x < 6)   sb[threadIdx.x] = b[threadIdx.x];
    __syncthreads();

    for (int idx = threadIdx.x; idx < 6 * 144; idx += 256) {
        int c = idx / 144, r = idx % 144;
        int py = r / 12, px = r % 12;
        const float* wc = sw + c * 25;
        float m = -1e30f;
        #pragma unroll
        for (int dy = 0; dy < 2; dy++) {
            #pragma unroll
            for (int dx = 0; dx < 2; dx++) {
                int oy = 2 * py + dy, ox = 2 * px + dx;
                float s = 0.f;
                #pragma unroll
                for (int ky = 0; ky < 5; ky++) {
                    #pragma unroll
                    for (int kx = 0; kx < 5; kx++)
                        s = fmaf(si[(oy + ky) * 28 + ox + kx], wc[ky * 5 + kx], s);
                }
                m = fmaxf(m, s);
            }
        }
        g_pool1[(size_t)n * 864 + idx] = fmaxf(m + sb[c], 0.f);
    }
}

// ---------------- conv2 (6->16, 5x5) + maxpool2 + relu ----------------
// one block per image; 256 threads = 16*4*4 outputs, one per thread
__global__ __launch_bounds__(256) void conv2_kernel(const float* __restrict__ w,
                                                    const float* __restrict__ b) {
    __shared__ float si[864];
    __shared__ float sw[2400];
    __shared__ float sb[16];
    int n = blockIdx.x;
    const float* ip = g_pool1 + (size_t)n * 864;
    for (int i = threadIdx.x; i < 864; i += 256)  si[i] = ip[i];
    for (int i = threadIdx.x; i < 2400; i += 256) sw[i] = w[i];
    if (threadIdx.x < 16) sb[threadIdx.x] = b[threadIdx.x];
    __syncthreads();

    int tid = threadIdx.x;
    int c = tid >> 4, r = tid & 15;
    int py = r >> 2, px = r & 3;
    float m = -1e30f;
    #pragma unroll
    for (int dy = 0; dy < 2; dy++) {
        #pragma unroll
        for (int dx = 0; dx < 2; dx++) {
            int oy = 2 * py + dy, ox = 2 * px + dx;
            float s = 0.f;
            #pragma unroll
            for (int ic = 0; ic < 6; ic++) {
                const float* wp = sw + c * 150 + ic * 25;
                const float* xp = si + ic * 144 + oy * 12 + ox;
                #pragma unroll
                for (int ky = 0; ky < 5; ky++) {
                    #pragma unroll
                    for (int kx = 0; kx < 5; kx++)
                        s = fmaf(xp[ky * 12 + kx], wp[ky * 5 + kx], s);
                }
            }
            m = fmaxf(m, s);
        }
    }
    // tid == c*16 + py*4 + px exactly -> NCHW-flatten order matches reshape
    g_pool2[(size_t)n * 256 + tid] = fmaxf(m + sb[c], 0.f);
}

// ---------------- fused FC1+FC2+FC3+log_softmax ----------------
// 8 images per block, 128 threads; thread j owns neuron j for all 8 images
#define FCI 8
__global__ __launch_bounds__(128) void fc_kernel(const float* __restrict__ b1,
                                                 const float* __restrict__ b2,
                                                 const float* __restrict__ b3) {
    __shared__ float xs[FCI][256];
    __shared__ float h1[FCI][120];
    __shared__ float h2[FCI][84];
    __shared__ float h3[FCI][10];
    int n0 = blockIdx.x * FCI;
    const float* xp = g_pool2 + (size_t)n0 * 256;
    for (int i = threadIdx.x; i < FCI * 256; i += 128) xs[i >> 8][i & 255] = xp[i];
    __syncthreads();

    int j = threadIdx.x;
    if (j < 120) {
        float acc[FCI];
        float bb = b1[j];
        #pragma unroll
        for (int im = 0; im < FCI; im++) acc[im] = bb;
        for (int k = 0; k < 256; k++) {
            float wv = g_w1t[k * 120 + j];
            #pragma unroll
            for (int im = 0; im < FCI; im++) acc[im] = fmaf(xs[im][k], wv, acc[im]);
        }
        #pragma unroll
        for (int im = 0; im < FCI; im++) h1[im][j] = fmaxf(acc[im], 0.f);
    }
    __syncthreads();
    if (j < 84) {
        float acc[FCI];
        float bb = b2[j];
        #pragma unroll
        for (int im = 0; im < FCI; im++) acc[im] = bb;
        for (int k = 0; k < 120; k++) {
            float wv = g_w2t[k * 84 + j];
            #pragma unroll
            for (int im = 0; im < FCI; im++) acc[im] = fmaf(h1[im][k], wv, acc[im]);
        }
        #pragma unroll
        for (int im = 0; im < FCI; im++) h2[im][j] = fmaxf(acc[im], 0.f);
    }
    __syncthreads();
    if (j < FCI * 10) {
        int im = j / 10, jj = j % 10;
        float acc = b3[jj];
        #pragma unroll
        for (int k = 0; k < 84; k++) acc = fmaf(h2[im][k], g_w3t[k * 10 + jj], acc);
        h3[im][jj] = acc;
    }
    __syncthreads();
    if (j < FCI) {
        float m = -1e30f;
        #pragma unroll
        for (int d = 0; d < 10; d++) m = fmaxf(m, h3[j][d]);
        float s = 0.f;
        #pragma unroll
        for (int d = 0; d < 10; d++) s += __expf(h3[j][d] - m);
        float lse = m + __logf(s);
        float* op = g_logp + (size_t)(n0 + j) * 10;
        #pragma unroll
        for (int d = 0; d < 10; d++) op[d] = h3[j][d] - lse;
    }
}

// ---------------- probabilistic circuit: segment logsumexp over i+j=s ----------------
// one block per batch item; 199 active threads, one per output sum value
__global__ __launch_bounds__(256) void circuit_kernel(float* __restrict__ out) {
    __shared__ float lp[40];
    __shared__ float lp1[100];
    __shared__ float lp2[100];
    int bI = blockIdx.x;
    int t = threadIdx.x;
    if (t < 40) lp[t] = g_logp[(size_t)bI * 40 + t];
    __syncthreads();
    if (t < 100) {
        lp1[t] = lp[0 + t / 10] + lp[10 + t % 10];
    } else if (t < 200) {
        int k = t - 100;
        lp2[k] = lp[20 + k / 10] + lp[30 + k % 10];
    }
    __syncthreads();
    if (t < SUMS) {
        int lo = t > 99 ? t - 99 : 0;
        int hi = t < 99 ? t : 99;
        float m = -1e30f;
        for (int i = lo; i <= hi; i++) m = fmaxf(m, lp1[i] + lp2[t - i]);
        float s = 0.f;
        for (int i = lo; i <= hi; i++) s += __expf(lp1[i] + lp2[t - i] - m);
        out[(size_t)bI * SUMS + t] = m + __logf(s);
    }
}

// ---------------- launch ----------------
extern "C" void kernel_launch(void* const* d_in, const int* in_sizes, int n_in,
                              void* d_out, int out_size) {
    const float* images = (const float*)d_in[0];
    const float* c1w    = (const float*)d_in[1];
    const float* c1b    = (const float*)d_in[2];
    const float* c2w    = (const float*)d_in[3];
    const float* c2b    = (const float*)d_in[4];
    const float* f1w    = (const float*)d_in[5];
    const float* f1b    = (const float*)d_in[6];
    const float* f2w    = (const float*)d_in[7];
    const float* f2b    = (const float*)d_in[8];
    const float* f3w    = (const float*)d_in[9];
    const float* f3b    = (const float*)d_in[10];
    float* out = (float*)d_out;

    transpose_kernel<<<(120 * 256 + 255) / 256, 256>>>(f1w, f2w, f3w);
    conv1_kernel<<<N_IMG, 256>>>(images, c1w, c1b);
    conv2_kernel<<<N_IMG, 256>>>(c2w, c2b);
    fc_kernel<<<N_IMG / FCI, 128>>>(f1b, f2b, f3b);
    circuit_kernel<<<NBATCH, 256>>>(out);
}

// round 2
// speedup vs baseline: 1.0050x; 1.0050x over previous
#include <cuda_runtime.h>
#include <cuda_bf16.h>
#include <math.h>

// ---------------- problem constants ----------------
#define N_IMG   16384           // B * 2 * NB_DIGITS
#define NPAIR   (N_IMG / 2)
#define NBATCH  4096
#define SUMS    199

typedef unsigned long long ull;

// ---------------- f32x2 packed helpers (Blackwell FFMA2 path) ----------------
__device__ __forceinline__ ull ffma2(ull a, ull b, ull c) {
    ull d;
    asm("fma.rn.f32x2 %0, %1, %2, %3;" : "=l"(d) : "l"(a), "l"(b), "l"(c));
    return d;
}
__device__ __forceinline__ ull pack2(float lo, float hi) {
    ull r;
    asm("mov.b64 %0, {%1, %2};" : "=l"(r) : "f"(lo), "f"(hi));
    return r;
}
__device__ __forceinline__ float2 unpack2(ull v) {
    float2 f;
    asm("mov.b64 {%0, %1}, %2;" : "=f"(f.x), "=f"(f.y) : "l"(v));
    return f;
}

// ---------------- device scratch (pair-interleaved: one ull = {imgA,imgB}) ----
__device__ ull   g_pool1p[(size_t)NPAIR * 864];   // after conv1+pool+relu
__device__ ull   g_pool2p[(size_t)NPAIR * 256];   // after conv2+pool+relu (flattened NCHW)
__device__ float g_logp [(size_t)N_IMG * 10];     // per-image log-softmax
__device__ float g_w1t[256 * 120];                // fc1_w transposed [k][j]
__device__ float g_w2t[120 * 84];
__device__ float g_w3t[84 * 10];

// ---------------- weight transposes ----------------
__global__ void transpose_kernel(const float* __restrict__ w1,
                                 const float* __restrict__ w2,
                                 const float* __restrict__ w3) {
    int i = blockIdx.x * blockDim.x + threadIdx.x;
    if (i < 120 * 256) { int j = i / 256, k = i % 256; g_w1t[k * 120 + j] = w1[i]; }
    if (i < 84 * 120)  { int j = i / 120, k = i % 120; g_w2t[k * 84 + j]  = w2[i]; }
    if (i < 10 * 84)   { int j = i / 84,  k = i % 84;  g_w3t[k * 10 + j]  = w3[i]; }
}

// ---------------- conv1 (1->6, 5x5) + maxpool2 + relu, f32x2 image pairs ------
// block = 4 images (2 pairs), 288 threads; thread owns one pooled position.
__global__ __launch_bounds__(288) void conv1_kernel(const float* __restrict__ img,
                                                    const float* __restrict__ w,
                                                    const float* __restrict__ b) {
    __shared__ ull   sp[2][784];
    __shared__ ull   swp[150];
    __shared__ float sb[6];
    int n0 = blockIdx.x * 4;
    int t = threadIdx.x;
    for (int i = t; i < 2 * 784; i += 288) {
        int q = i / 784, j = i % 784;
        sp[q][j] = pack2(img[(size_t)(n0 + 2 * q) * 784 + j],
                         img[(size_t)(n0 + 2 * q + 1) * 784 + j]);
    }
    if (t < 150) { float v = w[t]; swp[t] = pack2(v, v); }
    if (t < 6)   sb[t] = b[t];
    __syncthreads();

    int pairIdx = t / 144;            // 0..1
    int pos = t % 144;
    int py = pos / 12, px = pos % 12;
    const ull* si = sp[pairIdx];

    ull acc[6][4];
    #pragma unroll
    for (int ic = 0; ic < 6; ic++)
        #pragma unroll
        for (int q = 0; q < 4; q++) acc[ic][q] = 0ULL;

    #pragma unroll
    for (int ky = 0; ky < 5; ky++) {
        #pragma unroll
        for (int kx = 0; kx < 5; kx++) {
            int base = (2 * py + ky) * 28 + 2 * px + kx;
            ull x00 = si[base],      x01 = si[base + 1];
            ull x10 = si[base + 28], x11 = si[base + 29];
            #pragma unroll
            for (int ic = 0; ic < 6; ic++) {
                ull wq = swp[ic * 25 + ky * 5 + kx];
                acc[ic][0] = ffma2(x00, wq, acc[ic][0]);
                acc[ic][1] = ffma2(x01, wq, acc[ic][1]);
                acc[ic][2] = ffma2(x10, wq, acc[ic][2]);
                acc[ic][3] = ffma2(x11, wq, acc[ic][3]);
            }
        }
    }

    int pg = blockIdx.x * 2 + pairIdx;
    #pragma unroll
    for (int ic = 0; ic < 6; ic++) {
        float2 a = unpack2(acc[ic][0]), c2 = unpack2(acc[ic][1]);
        float2 d = unpack2(acc[ic][2]), e  = unpack2(acc[ic][3]);
        float bb = sb[ic];
        float oA = fmaxf(fmaxf(fmaxf(a.x, c2.x), fmaxf(d.x, e.x)) + bb, 0.f);
        float oB = fmaxf(fmaxf(fmaxf(a.y, c2.y), fmaxf(d.y, e.y)) + bb, 0.f);
        g_pool1p[(size_t)pg * 864 + ic * 144 + pos] = pack2(oA, oB);
    }
}

// ---------------- conv2 (6->16, 5x5) + maxpool2 + relu, f32x2 pairs -----------
// block = 8 images (4 pairs), 128 threads: pair(4) x pooledpos(16) x chgroup(2 of 8ch)
__global__ __launch_bounds__(128) void conv2_kernel(const float* __restrict__ w,
                                                    const float* __restrict__ b) {
    __shared__ ull   sp[4][864];
    __shared__ ull   swp[2400];
    __shared__ float sb[16];
    int p0 = blockIdx.x * 4;          // first pair
    int t = threadIdx.x;
    for (int i = t; i < 4 * 864; i += 128) {
        int q = i / 864, j = i % 864;
        sp[q][j] = g_pool1p[(size_t)(p0 + q) * 864 + j];
    }
    for (int i = t; i < 2400; i += 128) { float v = w[i]; swp[i] = pack2(v, v); }
    if (t < 16) sb[t] = b[t];
    __syncthreads();

    int pr  = t >> 5;
    int sub = t & 31;
    int pos = sub & 15;
    int cg  = sub >> 4;
    int py = pos >> 2, px = pos & 3;
    int c0 = cg * 8;
    const ull* si = sp[pr];

    ull acc[8][4];
    #pragma unroll
    for (int cc = 0; cc < 8; cc++)
        #pragma unroll
        for (int q = 0; q < 4; q++) acc[cc][q] = 0ULL;

    for (int ic = 0; ic < 6; ic++) {
        const ull* xi = si + ic * 144;
        const ull* wi = swp + c0 * 150 + ic * 25;
        #pragma unroll
        for (int ky = 0; ky < 5; ky++) {
            #pragma unroll
            for (int kx = 0; kx < 5; kx++) {
                int base = (2 * py + ky) * 12 + 2 * px + kx;
                ull x00 = xi[base],      x01 = xi[base + 1];
                ull x10 = xi[base + 12], x11 = xi[base + 13];
                #pragma unroll
                for (int cc = 0; cc < 8; cc++) {
                    ull wq = wi[cc * 150 + ky * 5 + kx];
                    acc[cc][0] = ffma2(x00, wq, acc[cc][0]);
                    acc[cc][1] = ffma2(x01, wq, acc[cc][1]);
                    acc[cc][2] = ffma2(x10, wq, acc[cc][2]);
                    acc[cc][3] = ffma2(x11, wq, acc[cc][3]);
                }
            }
        }
    }

    #pragma unroll
    for (int cc = 0; cc < 8; cc++) {
        float2 a = unpack2(acc[cc][0]), c2 = unpack2(acc[cc][1]);
        float2 d = unpack2(acc[cc][2]), e  = unpack2(acc[cc][3]);
        float bb = sb[c0 + cc];
        float oA = fmaxf(fmaxf(fmaxf(a.x, c2.x), fmaxf(d.x, e.x)) + bb, 0.f);
        float oB = fmaxf(fmaxf(fmaxf(a.y, c2.y), fmaxf(d.y, e.y)) + bb, 0.f);
        // NCHW flatten: idx = c*16 + py*4 + px
        g_pool2p[(size_t)(p0 + pr) * 256 + (c0 + cc) * 16 + py * 4 + px] = pack2(oA, oB);
    }
}

// ---------------- fused FC1+FC2+FC3+log_softmax, f32x2 pairs ------------------
// block = 8 pairs (16 images), 128 threads
#define FCP 8
__global__ __launch_bounds__(128) void fc_kernel(const float* __restrict__ b1,
                                                 const float* __restrict__ b2,
                                                 const float* __restrict__ b3) {
    __shared__ ull xs[FCP][256];
    __shared__ ull h1[FCP][120];
    __shared__ ull h2[FCP][84];
    __shared__ ull h3[FCP][10];
    int p0 = blockIdx.x * FCP;
    int t = threadIdx.x;
    for (int i = t; i < FCP * 256; i += 128)
        xs[i >> 8][i & 255] = g_pool2p[(size_t)p0 * 256 + i];
    __syncthreads();

    if (t < 120) {
        float bb = b1[t];
        ull bp = pack2(bb, bb);
        ull acc[FCP];
        #pragma unroll
        for (int p = 0; p < FCP; p++) acc[p] = bp;
        #pragma unroll 4
        for (int k = 0; k < 256; k++) {
            float wv = g_w1t[k * 120 + t];
            ull wq = pack2(wv, wv);
            #pragma unroll
            for (int p = 0; p < FCP; p++) acc[p] = ffma2(xs[p][k], wq, acc[p]);
        }
        #pragma unroll
        for (int p = 0; p < FCP; p++) {
            float2 u = unpack2(acc[p]);
            h1[p][t] = pack2(fmaxf(u.x, 0.f), fmaxf(u.y, 0.f));
        }
    }
    __syncthreads();
    if (t < 84) {
        float bb = b2[t];
        ull bp = pack2(bb, bb);
        ull acc[FCP];
        #pragma unroll
        for (int p = 0; p < FCP; p++) acc[p] = bp;
        #pragma unroll 4
        for (int k = 0; k < 120; k++) {
            float wv = g_w2t[k * 84 + t];
            ull wq = pack2(wv, wv);
            #pragma unroll
            for (int p = 0; p < FCP; p++) acc[p] = ffma2(h1[p][k], wq, acc[p]);
        }
        #pragma unroll
        for (int p = 0; p < FCP; p++) {
            float2 u = unpack2(acc[p]);
            h2[p][t] = pack2(fmaxf(u.x, 0.f), fmaxf(u.y, 0.f));
        }
    }
    __syncthreads();
    if (t < 80) {
        int p = t / 10, d = t % 10;
        float bb = b3[d];
        ull acc = pack2(bb, bb);
        #pragma unroll
        for (int k = 0; k < 84; k++) {
            float wv = g_w3t[k * 10 + d];
            acc = ffma2(h2[p][k], pack2(wv, wv), acc);
        }
        h3[p][d] = acc;
    }
    __syncthreads();
    if (t < 16) {
        int p = t >> 1, hf = t & 1;
        float v[10];
        #pragma unroll
        for (int d = 0; d < 10; d++) {
            float2 u = unpack2(h3[p][d]);
            v[d] = hf ? u.y : u.x;
        }
        float m = -1e30f;
        #pragma unroll
        for (int d = 0; d < 10; d++) m = fmaxf(m, v[d]);
        float s = 0.f;
        #pragma unroll
        for (int d = 0; d < 10; d++) s += __expf(v[d] - m);
        float lse = m + __logf(s);
        float* op = g_logp + (size_t)((p0 + p) * 2 + hf) * 10;
        #pragma unroll
        for (int d = 0; d < 10; d++) op[d] = v[d] - lse;
    }
}

// ---------------- probabilistic circuit: segment logsumexp over i+j=s ---------
__global__ __launch_bounds__(256) void circuit_kernel(float* __restrict__ out) {
    __shared__ float lp[40];
    __shared__ float lp1[100];
    __shared__ float lp2[100];
    int bI = blockIdx.x;
    int t = threadIdx.x;
    if (t < 40) lp[t] = g_logp[(size_t)bI * 40 + t];
    __syncthreads();
    if (t < 100) {
        lp1[t] = lp[0 + t / 10] + lp[10 + t % 10];
    } else if (t < 200) {
        int k = t - 100;
        lp2[k] = lp[20 + k / 10] + lp[30 + k % 10];
    }
    __syncthreads();
    if (t < SUMS) {
        int lo = t > 99 ? t - 99 : 0;
        int hi = t < 99 ? t : 99;
        float m = -1e30f;
        for (int i = lo; i <= hi; i++) m = fmaxf(m, lp1[i] + lp2[t - i]);
        float s = 0.f;
        for (int i = lo; i <= hi; i++) s += __expf(lp1[i] + lp2[t - i] - m);
        out[(size_t)bI * SUMS + t] = m + __logf(s);
    }
}

// ---------------- launch ----------------
extern "C" void kernel_launch(void* const* d_in, const int* in_sizes, int n_in,
                              void* d_out, int out_size) {
    const float* images = (const float*)d_in[0];
    const float* c1w    = (const float*)d_in[1];
    const float* c1b    = (const float*)d_in[2];
    const float* c2w    = (const float*)d_in[3];
    const float* c2b    = (const float*)d_in[4];
    const float* f1w    = (const float*)d_in[5];
    const float* f1b    = (const float*)d_in[6];
    const float* f2w    = (const float*)d_in[7];
    const float* f2b    = (const float*)d_in[8];
    const float* f3w    = (const float*)d_in[9];
    const float* f3b    = (const float*)d_in[10];
    float* out = (float*)d_out;

    transpose_kernel<<<(120 * 256 + 255) / 256, 256>>>(f1w, f2w, f3w);
    conv1_kernel<<<N_IMG / 4, 288>>>(images, c1w, c1b);
    conv2_kernel<<<N_IMG / 8, 128>>>(c2w, c2b);
    fc_kernel<<<NPAIR / FCP, 128>>>(f1b, f2b, f3b);
    circuit_kernel<<<NBATCH, 256>>>(out);
}